// round 1
// baseline (speedup 1.0000x reference)
#include <cuda_runtime.h>
#include <cstdint>

// Problem shape (from setup_inputs): x (4,64,80,80), coord (4,320,320,2), cell (4,2)
// Output: (4, 266, 320, 320) fp32, channels = [rel_coords s0..s3 (2 ea), feats s0..s3 (64 ea), cell_map (2)]
#define BB 4
#define CC 64
#define HH 80
#define WW 80
#define HO 320
#define WO 320
#define NCH 266

// Channel-last scratch: xT[b][y][x][c]
__device__ float g_xT[(size_t)BB * HH * WW * CC];

__global__ void transpose_kernel(const float* __restrict__ x) {
    int idx = blockIdx.x * blockDim.x + threadIdx.x;   // over B*H*W
    if (idx >= BB * HH * WW) return;
    int b  = idx / (HH * WW);
    int yw = idx % (HH * WW);
    const float* src = x + (size_t)b * CC * HH * WW + yw;
    float* dst = g_xT + (size_t)idx * CC;
#pragma unroll
    for (int c = 0; c < CC; c += 4) {
        float4 v;
        v.x = src[(size_t)(c + 0) * HH * WW];
        v.y = src[(size_t)(c + 1) * HH * WW];
        v.z = src[(size_t)(c + 2) * HH * WW];
        v.w = src[(size_t)(c + 3) * HH * WW];
        *reinterpret_cast<float4*>(dst + c) = v;
    }
}

__global__ __launch_bounds__(256) void liif_kernel(const float* __restrict__ coord,
                                                   const float* __restrict__ cell,
                                                   float* __restrict__ out) {
    int ox = blockIdx.x * blockDim.x + threadIdx.x;
    int oy = blockIdx.y * blockDim.y + threadIdx.y;
    int b  = blockIdx.z;
    if (ox >= WO || oy >= HO) return;

    const size_t pix = ((size_t)b * HO + oy) * WO + ox;
    const float cyd = coord[pix * 2 + 0];
    const float cxd = coord[pix * 2 + 1];

    const float rx  = 1.0f / HH;   // note: reference uses rx = 1/H (applied to y shift)
    const float ry  = 1.0f / WW;   //       and ry = 1/W (applied to x shift)
    const float eps = 1e-6f;

    const float* __restrict__ xTb = g_xT + (size_t)b * HH * WW * CC;

    int   base[16];
    float cw[16];
    float area[4], rel0s[4], rel1s[4];

#pragma unroll
    for (int s = 0; s < 4; s++) {
        const float vx = (s < 2) ? -1.0f : 1.0f;   // outer loop over vx
        const float vy = (s & 1) ? 1.0f : -1.0f;   // inner loop over vy
        float cy = fminf(fmaxf(cyd + vx * rx + eps, -1.0f + 1e-6f), 1.0f - 1e-6f);
        float cx = fminf(fmaxf(cxd + vy * ry + eps, -1.0f + 1e-6f), 1.0f - 1e-6f);

        // grid_sample (align_corners=False) pixel coords
        float iy = ((cy + 1.0f) * HH - 1.0f) * 0.5f;
        float ix = ((cx + 1.0f) * WW - 1.0f) * 0.5f;
        float y0f = floorf(iy), x0f = floorf(ix);
        float wy1 = iy - y0f,  wx1 = ix - x0f;
        float wy0 = 1.0f - wy1, wx0 = 1.0f - wx1;

        float oldy = 0.0f, oldx = 0.0f;
#pragma unroll
        for (int k = 0; k < 4; k++) {
            const float yf = y0f + (float)(k >> 1);
            const float xf = x0f + (float)(k & 1);
            const float w  = ((k >> 1) ? wy1 : wy0) * ((k & 1) ? wx1 : wx0);
            const float m  = (xf >= 0.0f && xf <= (float)(WW - 1) &&
                              yf >= 0.0f && yf <= (float)(HH - 1)) ? 1.0f : 0.0f;
            const int yc = (int)fminf(fmaxf(yf, 0.0f), (float)(HH - 1));
            const int xc = (int)fminf(fmaxf(xf, 0.0f), (float)(WW - 1));
            const float mw = m * w;
            base[s * 4 + k] = (yc * WW + xc) * CC;
            cw[s * 4 + k]   = mw;
            // pos_lr is analytic: ch0 = (2y+1)/H - 1, ch1 = (2x+1)/W - 1
            oldy += mw * ((2.0f * (float)yc + 1.0f) / (float)HH - 1.0f);
            oldx += mw * ((2.0f * (float)xc + 1.0f) / (float)WW - 1.0f);
        }
        const float r0 = (cyd - oldy) * (float)HH;
        const float r1 = (cxd - oldx) * (float)WW;
        rel0s[s] = r0;
        rel1s[s] = r1;
        area[s]  = fabsf(r0 * r1) + 1e-9f;
    }

    const float tot = area[0] + area[1] + area[2] + area[3];
    float wgt[4];
#pragma unroll
    for (int s = 0; s < 4; s++) wgt[s] = area[3 - s] / tot;

    const size_t cs   = (size_t)HO * WO;
    const size_t opix = (size_t)b * NCH * cs + (size_t)oy * WO + ox;

    // rel_coords: channels 0..7
#pragma unroll
    for (int s = 0; s < 4; s++) {
        out[opix + (size_t)(2 * s + 0) * cs] = rel0s[s];
        out[opix + (size_t)(2 * s + 1) * cs] = rel1s[s];
    }
    // cell_map: channels 264, 265
    out[opix + (size_t)264 * cs] = cell[b * 2 + 0] * (float)HH;
    out[opix + (size_t)265 * cs] = cell[b * 2 + 1] * (float)WW;

    // feats: channels 8 + s*64 + c
#pragma unroll
    for (int s = 0; s < 4; s++) {
        const float w0 = cw[s * 4 + 0] * wgt[s];
        const float w1 = cw[s * 4 + 1] * wgt[s];
        const float w2 = cw[s * 4 + 2] * wgt[s];
        const float w3 = cw[s * 4 + 3] * wgt[s];
        const float* __restrict__ p0 = xTb + base[s * 4 + 0];
        const float* __restrict__ p1 = xTb + base[s * 4 + 1];
        const float* __restrict__ p2 = xTb + base[s * 4 + 2];
        const float* __restrict__ p3 = xTb + base[s * 4 + 3];
        const size_t och = opix + (size_t)(8 + s * 64) * cs;
#pragma unroll
        for (int c = 0; c < CC; c += 4) {
            const float4 a  = *reinterpret_cast<const float4*>(p0 + c);
            const float4 bv = *reinterpret_cast<const float4*>(p1 + c);
            const float4 cv = *reinterpret_cast<const float4*>(p2 + c);
            const float4 dv = *reinterpret_cast<const float4*>(p3 + c);
            out[och + (size_t)(c + 0) * cs] = w0 * a.x + w1 * bv.x + w2 * cv.x + w3 * dv.x;
            out[och + (size_t)(c + 1) * cs] = w0 * a.y + w1 * bv.y + w2 * cv.y + w3 * dv.y;
            out[och + (size_t)(c + 2) * cs] = w0 * a.z + w1 * bv.z + w2 * cv.z + w3 * dv.z;
            out[och + (size_t)(c + 3) * cs] = w0 * a.w + w1 * bv.w + w2 * cv.w + w3 * dv.w;
        }
    }
}

extern "C" void kernel_launch(void* const* d_in, const int* in_sizes, int n_in,
                              void* d_out, int out_size) {
    const float* x     = (const float*)d_in[0];   // (4,64,80,80)
    const float* coord = (const float*)d_in[1];   // (4,320,320,2)
    const float* cell  = (const float*)d_in[2];   // (4,2)
    float* out = (float*)d_out;                   // (4,266,320,320)

    {
        int n = BB * HH * WW;
        transpose_kernel<<<(n + 255) / 256, 256>>>(x);
    }
    {
        dim3 block(32, 8);
        dim3 grid((WO + 31) / 32, (HO + 7) / 8, BB);
        liif_kernel<<<grid, block>>>(coord, cell, out);
    }
}

// round 2
// speedup vs baseline: 1.4713x; 1.4713x over previous
#include <cuda_runtime.h>
#include <cstdint>

#define BB 4
#define CC 64
#define HH 80
#define WW 80
#define HO 320
#define WO 320
#define NCH 266

// Channel-last scratch: xT[b][y][x][c]
__device__ float g_xT[(size_t)BB * HH * WW * CC];

__global__ void transpose_kernel(const float* __restrict__ x) {
    int idx = blockIdx.x * blockDim.x + threadIdx.x;   // over B*H*W
    if (idx >= BB * HH * WW) return;
    int b  = idx / (HH * WW);
    int yw = idx % (HH * WW);
    const float* src = x + (size_t)b * CC * HH * WW + yw;
    float* dst = g_xT + (size_t)idx * CC;
#pragma unroll
    for (int c = 0; c < CC; c += 4) {
        float4 v;
        v.x = src[(size_t)(c + 0) * HH * WW];
        v.y = src[(size_t)(c + 1) * HH * WW];
        v.z = src[(size_t)(c + 2) * HH * WW];
        v.w = src[(size_t)(c + 3) * HH * WW];
        *reinterpret_cast<float4*>(dst + c) = v;
    }
}

// One output pixel per thread. All 16 bilinear corners live in a shared 3x3
// input patch (ensemble shift = exactly 0.5 input px). Weights are separable:
// corner weight = (my*wy) * (mx*wx). Build Wf[4][9] once, then the channel
// loop is 9 float4 loads -> 4 outputs.
__global__ __launch_bounds__(256) void liif_kernel(const float* __restrict__ coord,
                                                   const float* __restrict__ cell,
                                                   float* __restrict__ out) {
    int ox = blockIdx.x * blockDim.x + threadIdx.x;
    int oy = blockIdx.y * blockDim.y + threadIdx.y;
    int b  = blockIdx.z;
    if (ox >= WO || oy >= HO) return;

    const size_t pix = ((size_t)b * HO + oy) * WO + ox;
    const float cyd = coord[pix * 2 + 0];
    const float cxd = coord[pix * 2 + 1];

    const float rshift_y = 1.0f / HH;   // reference rx (applied to y)
    const float rshift_x = 1.0f / WW;   // reference ry (applied to x)
    const float eps = 1e-6f;
    const float lo = -1.0f + 1e-6f, hi = 1.0f - 1e-6f;

    // ---- y dimension: two shifts (m = -, p = +) over a 3-row window ----
    float ay[2][3], Sy[2], My[2];
    int   ryc[3];
    {
        float cym = fminf(fmaxf(cyd - rshift_y + eps, lo), hi);
        float cyp = fminf(fmaxf(cyd + rshift_y + eps, lo), hi);
        float iym = ((cym + 1.0f) * HH - 1.0f) * 0.5f;
        float iyp = ((cyp + 1.0f) * HH - 1.0f) * 0.5f;
        float y0m = floorf(iym), y0p = floorf(iyp);
        float wy1m = iym - y0m, wy0m = 1.0f - wy1m;
        float wy1p = iyp - y0p, wy0p = 1.0f - wy1p;
        int Y = (int)y0m;
        bool d = (y0p != y0m);            // 0 or 1 row offset
        float m0 = (Y     >= 0 && Y     <= HH - 1) ? 1.0f : 0.0f;
        float m1 = (Y + 1 >= 0 && Y + 1 <= HH - 1) ? 1.0f : 0.0f;
        float m2 = (Y + 2 >= 0 && Y + 2 <= HH - 1) ? 1.0f : 0.0f;
        ay[0][0] = m0 * wy0m; ay[0][1] = m1 * wy1m; ay[0][2] = 0.0f;
        ay[1][0] = d ? 0.0f : m0 * wy0p;
        ay[1][1] = d ? m1 * wy0p : m1 * wy1p;
        ay[1][2] = d ? m2 * wy1p : 0.0f;
#pragma unroll
        for (int j = 0; j < 3; j++) ryc[j] = min(max(Y + j, 0), HH - 1);
        float py0 = (2.0f * ryc[0] + 1.0f) / HH - 1.0f;
        float py1 = (2.0f * ryc[1] + 1.0f) / HH - 1.0f;
        float py2 = (2.0f * ryc[2] + 1.0f) / HH - 1.0f;
#pragma unroll
        for (int t = 0; t < 2; t++) {
            Sy[t] = ay[t][0] * py0 + ay[t][1] * py1 + ay[t][2] * py2;
            My[t] = ay[t][0] + ay[t][1] + ay[t][2];
        }
    }

    // ---- x dimension ----
    float ax[2][3], Sx[2], Mx[2];
    int   rxc[3];
    {
        float cxm = fminf(fmaxf(cxd - rshift_x + eps, lo), hi);
        float cxp = fminf(fmaxf(cxd + rshift_x + eps, lo), hi);
        float ixm = ((cxm + 1.0f) * WW - 1.0f) * 0.5f;
        float ixp = ((cxp + 1.0f) * WW - 1.0f) * 0.5f;
        float x0m = floorf(ixm), x0p = floorf(ixp);
        float wx1m = ixm - x0m, wx0m = 1.0f - wx1m;
        float wx1p = ixp - x0p, wx0p = 1.0f - wx1p;
        int X = (int)x0m;
        bool d = (x0p != x0m);
        float m0 = (X     >= 0 && X     <= WW - 1) ? 1.0f : 0.0f;
        float m1 = (X + 1 >= 0 && X + 1 <= WW - 1) ? 1.0f : 0.0f;
        float m2 = (X + 2 >= 0 && X + 2 <= WW - 1) ? 1.0f : 0.0f;
        ax[0][0] = m0 * wx0m; ax[0][1] = m1 * wx1m; ax[0][2] = 0.0f;
        ax[1][0] = d ? 0.0f : m0 * wx0p;
        ax[1][1] = d ? m1 * wx0p : m1 * wx1p;
        ax[1][2] = d ? m2 * wx1p : 0.0f;
#pragma unroll
        for (int j = 0; j < 3; j++) rxc[j] = min(max(X + j, 0), WW - 1);
        float px0 = (2.0f * rxc[0] + 1.0f) / WW - 1.0f;
        float px1 = (2.0f * rxc[1] + 1.0f) / WW - 1.0f;
        float px2 = (2.0f * rxc[2] + 1.0f) / WW - 1.0f;
#pragma unroll
        for (int t = 0; t < 2; t++) {
            Sx[t] = ax[t][0] * px0 + ax[t][1] * px1 + ax[t][2] * px2;
            Mx[t] = ax[t][0] + ax[t][1] + ax[t][2];
        }
    }

    // ---- per-shift rel coords + areas ----
    float area[4], rel0s[4], rel1s[4];
#pragma unroll
    for (int s = 0; s < 4; s++) {
        const int sy = s >> 1, sx = s & 1;
        float oldy = Sy[sy] * Mx[sx];
        float oldx = My[sy] * Sx[sx];
        float r0 = (cyd - oldy) * (float)HH;
        float r1 = (cxd - oldx) * (float)WW;
        rel0s[s] = r0; rel1s[s] = r1;
        area[s] = fabsf(r0 * r1) + 1e-9f;
    }
    const float tot = area[0] + area[1] + area[2] + area[3];

    // ---- combined 3x3 weights per shift (ensemble weight folded in) ----
    float Wf[4][9];
#pragma unroll
    for (int s = 0; s < 4; s++) {
        const int sy = s >> 1, sx = s & 1;
        const float wgt = area[3 - s] / tot;
#pragma unroll
        for (int jy = 0; jy < 3; jy++)
#pragma unroll
            for (int jx = 0; jx < 3; jx++)
                Wf[s][jy * 3 + jx] = ay[sy][jy] * ax[sx][jx] * wgt;
    }

    // ---- patch base offsets ----
    const float* __restrict__ xTb = g_xT + (size_t)b * HH * WW * CC;
    int off[9];
#pragma unroll
    for (int jy = 0; jy < 3; jy++)
#pragma unroll
        for (int jx = 0; jx < 3; jx++)
            off[jy * 3 + jx] = (ryc[jy] * WW + rxc[jx]) * CC;

    const size_t cs   = (size_t)HO * WO;
    const size_t opix = (size_t)b * NCH * cs + (size_t)oy * WO + ox;

    // rel_coords: channels 0..7
#pragma unroll
    for (int s = 0; s < 4; s++) {
        __stcs(&out[opix + (size_t)(2 * s + 0) * cs], rel0s[s]);
        __stcs(&out[opix + (size_t)(2 * s + 1) * cs], rel1s[s]);
    }
    // cell_map: channels 264, 265
    __stcs(&out[opix + (size_t)264 * cs], cell[b * 2 + 0] * (float)HH);
    __stcs(&out[opix + (size_t)265 * cs], cell[b * 2 + 1] * (float)WW);

    // feats: channels 8 + s*64 + c ; 9 loads serve all 4 shifts
#pragma unroll 4
    for (int c = 0; c < CC; c += 4) {
        float4 f[9];
#pragma unroll
        for (int j = 0; j < 9; j++)
            f[j] = *reinterpret_cast<const float4*>(xTb + off[j] + c);
#pragma unroll
        for (int s = 0; s < 4; s++) {
            float4 acc = make_float4(0.f, 0.f, 0.f, 0.f);
#pragma unroll
            for (int j = 0; j < 9; j++) {
                const float w = Wf[s][j];
                acc.x += w * f[j].x;
                acc.y += w * f[j].y;
                acc.z += w * f[j].z;
                acc.w += w * f[j].w;
            }
            const size_t och = opix + (size_t)(8 + s * 64 + c) * cs;
            __stcs(&out[och + 0 * cs], acc.x);
            __stcs(&out[och + 1 * cs], acc.y);
            __stcs(&out[och + 2 * cs], acc.z);
            __stcs(&out[och + 3 * cs], acc.w);
        }
    }
}

extern "C" void kernel_launch(void* const* d_in, const int* in_sizes, int n_in,
                              void* d_out, int out_size) {
    const float* x     = (const float*)d_in[0];   // (4,64,80,80)
    const float* coord = (const float*)d_in[1];   // (4,320,320,2)
    const float* cell  = (const float*)d_in[2];   // (4,2)
    float* out = (float*)d_out;                   // (4,266,320,320)

    {
        int n = BB * HH * WW;
        transpose_kernel<<<(n + 255) / 256, 256>>>(x);
    }
    {
        dim3 block(32, 8);
        dim3 grid((WO + 31) / 32, (HO + 7) / 8, BB);
        liif_kernel<<<grid, block>>>(coord, cell, out);
    }
}

// round 3
// speedup vs baseline: 1.7532x; 1.1916x over previous
#include <cuda_runtime.h>
#include <cstdint>

#define BB 4
#define CC 64
#define HH 80
#define WW 80
#define HO 320
#define WO 320
#define NCH 266
#define TP   76      // floats per tile pixel (64 + pad; 19*dp mod 32 distinct for dp 0..8 -> conflict-free)
#define TMAXR 6
#define TMAXC 12

// Channel-last scratch: xT[b][y][x][c]
__device__ float g_xT[(size_t)BB * HH * WW * CC];

__global__ void transpose_kernel(const float* __restrict__ x) {
    int idx = blockIdx.x * blockDim.x + threadIdx.x;   // over B*H*W
    if (idx >= BB * HH * WW) return;
    int b  = idx / (HH * WW);
    int yw = idx % (HH * WW);
    const float* src = x + (size_t)b * CC * HH * WW + yw;
    float* dst = g_xT + (size_t)idx * CC;
#pragma unroll
    for (int c = 0; c < CC; c += 4) {
        float4 v;
        v.x = src[(size_t)(c + 0) * HH * WW];
        v.y = src[(size_t)(c + 1) * HH * WW];
        v.z = src[(size_t)(c + 2) * HH * WW];
        v.w = src[(size_t)(c + 3) * HH * WW];
        *reinterpret_cast<float4*>(dst + c) = v;
    }
}

__global__ __launch_bounds__(256) void liif_kernel(const float* __restrict__ coord,
                                                   const float* __restrict__ cell,
                                                   float* __restrict__ out) {
    __shared__ float tile[TMAXR * TMAXC * TP];   // 21.9 KB

    const int tid = threadIdx.y * 32 + threadIdx.x;
    const int ox  = blockIdx.x * 32 + threadIdx.x;
    const int oy  = blockIdx.y * 8  + threadIdx.y;
    const int b   = blockIdx.z;

    const size_t pix = ((size_t)b * HO + oy) * WO + ox;
    const float cyd = coord[pix * 2 + 0];
    const float cxd = coord[pix * 2 + 1];

    const float rshift_y = 1.0f / HH;
    const float rshift_x = 1.0f / WW;
    const float eps = 1e-6f;
    const float lo = -1.0f + 1e-6f, hi = 1.0f - 1e-6f;

    // ---- block-uniform tile bounds from corner coords (coord grid is monotone) ----
    const int oy0 = blockIdx.y * 8, ox0 = blockIdx.x * 32;
    const float* cB = coord + (size_t)b * HO * WO * 2;
    const float cyF = cB[((size_t)oy0 * WO + ox0) * 2 + 0];
    const float cyL = cB[((size_t)(oy0 + 7) * WO + ox0) * 2 + 0];
    const float cxF = cB[((size_t)oy0 * WO + ox0) * 2 + 1];
    const float cxL = cB[((size_t)oy0 * WO + (ox0 + 31)) * 2 + 1];

    int rowLo, nr, colLo, nc;
    {
        float ylo = ((fminf(fmaxf(cyF - rshift_y + eps, lo), hi) + 1.0f) * HH - 1.0f) * 0.5f;
        float yhi = ((fminf(fmaxf(cyL + rshift_y + eps, lo), hi) + 1.0f) * HH - 1.0f) * 0.5f;
        rowLo = max(0, (int)floorf(ylo));
        int rowHi = min(HH - 1, (int)floorf(yhi) + 1);
        nr = min(rowHi - rowLo + 1, TMAXR);
        float xlo = ((fminf(fmaxf(cxF - rshift_x + eps, lo), hi) + 1.0f) * WW - 1.0f) * 0.5f;
        float xhi = ((fminf(fmaxf(cxL + rshift_x + eps, lo), hi) + 1.0f) * WW - 1.0f) * 0.5f;
        colLo = max(0, (int)floorf(xlo));
        int colHi = min(WW - 1, (int)floorf(xhi) + 1);
        nc = min(colHi - colLo + 1, TMAXC);
    }

    // ---- per-thread geometry (identical math to prior round) ----
    float ay[2][3], Sy[2], My[2];
    int   ryc[3];
    {
        float cym = fminf(fmaxf(cyd - rshift_y + eps, lo), hi);
        float cyp = fminf(fmaxf(cyd + rshift_y + eps, lo), hi);
        float iym = ((cym + 1.0f) * HH - 1.0f) * 0.5f;
        float iyp = ((cyp + 1.0f) * HH - 1.0f) * 0.5f;
        float y0m = floorf(iym), y0p = floorf(iyp);
        float wy1m = iym - y0m, wy0m = 1.0f - wy1m;
        float wy1p = iyp - y0p, wy0p = 1.0f - wy1p;
        int Y = (int)y0m;
        bool d = (y0p != y0m);
        float m0 = (Y     >= 0 && Y     <= HH - 1) ? 1.0f : 0.0f;
        float m1 = (Y + 1 >= 0 && Y + 1 <= HH - 1) ? 1.0f : 0.0f;
        float m2 = (Y + 2 >= 0 && Y + 2 <= HH - 1) ? 1.0f : 0.0f;
        ay[0][0] = m0 * wy0m; ay[0][1] = m1 * wy1m; ay[0][2] = 0.0f;
        ay[1][0] = d ? 0.0f : m0 * wy0p;
        ay[1][1] = d ? m1 * wy0p : m1 * wy1p;
        ay[1][2] = d ? m2 * wy1p : 0.0f;
#pragma unroll
        for (int j = 0; j < 3; j++) ryc[j] = min(max(Y + j, 0), HH - 1);
        float py0 = (2.0f * ryc[0] + 1.0f) / HH - 1.0f;
        float py1 = (2.0f * ryc[1] + 1.0f) / HH - 1.0f;
        float py2 = (2.0f * ryc[2] + 1.0f) / HH - 1.0f;
#pragma unroll
        for (int t = 0; t < 2; t++) {
            Sy[t] = ay[t][0] * py0 + ay[t][1] * py1 + ay[t][2] * py2;
            My[t] = ay[t][0] + ay[t][1] + ay[t][2];
        }
    }

    float ax[2][3], Sx[2], Mx[2];
    int   rxc[3];
    {
        float cxm = fminf(fmaxf(cxd - rshift_x + eps, lo), hi);
        float cxp = fminf(fmaxf(cxd + rshift_x + eps, lo), hi);
        float ixm = ((cxm + 1.0f) * WW - 1.0f) * 0.5f;
        float ixp = ((cxp + 1.0f) * WW - 1.0f) * 0.5f;
        float x0m = floorf(ixm), x0p = floorf(ixp);
        float wx1m = ixm - x0m, wx0m = 1.0f - wx1m;
        float wx1p = ixp - x0p, wx0p = 1.0f - wx1p;
        int X = (int)x0m;
        bool d = (x0p != x0m);
        float m0 = (X     >= 0 && X     <= WW - 1) ? 1.0f : 0.0f;
        float m1 = (X + 1 >= 0 && X + 1 <= WW - 1) ? 1.0f : 0.0f;
        float m2 = (X + 2 >= 0 && X + 2 <= WW - 1) ? 1.0f : 0.0f;
        ax[0][0] = m0 * wx0m; ax[0][1] = m1 * wx1m; ax[0][2] = 0.0f;
        ax[1][0] = d ? 0.0f : m0 * wx0p;
        ax[1][1] = d ? m1 * wx0p : m1 * wx1p;
        ax[1][2] = d ? m2 * wx1p : 0.0f;
#pragma unroll
        for (int j = 0; j < 3; j++) rxc[j] = min(max(X + j, 0), WW - 1);
        float px0 = (2.0f * rxc[0] + 1.0f) / WW - 1.0f;
        float px1 = (2.0f * rxc[1] + 1.0f) / WW - 1.0f;
        float px2 = (2.0f * rxc[2] + 1.0f) / WW - 1.0f;
#pragma unroll
        for (int t = 0; t < 2; t++) {
            Sx[t] = ax[t][0] * px0 + ax[t][1] * px1 + ax[t][2] * px2;
            Mx[t] = ax[t][0] + ax[t][1] + ax[t][2];
        }
    }

    float area[4], rel0s[4], rel1s[4];
#pragma unroll
    for (int s = 0; s < 4; s++) {
        const int sy = s >> 1, sx = s & 1;
        float oldy = Sy[sy] * Mx[sx];
        float oldx = My[sy] * Sx[sx];
        float r0 = (cyd - oldy) * (float)HH;
        float r1 = (cxd - oldx) * (float)WW;
        rel0s[s] = r0; rel1s[s] = r1;
        area[s] = fabsf(r0 * r1) + 1e-9f;
    }
    const float tot = area[0] + area[1] + area[2] + area[3];

    // x weights with ensemble weight folded in
    float axw[4][3];
#pragma unroll
    for (int s = 0; s < 4; s++) {
        const float wgt = area[3 - s] / tot;
#pragma unroll
        for (int jx = 0; jx < 3; jx++)
            axw[s][jx] = ax[s & 1][jx] * wgt;
    }

    const size_t cs   = (size_t)HO * WO;
    const size_t opix = (size_t)b * NCH * cs + (size_t)oy * WO + ox;

    // rel_coords: channels 0..7
#pragma unroll
    for (int s = 0; s < 4; s++) {
        __stcs(&out[opix + (size_t)(2 * s + 0) * cs], rel0s[s]);
        __stcs(&out[opix + (size_t)(2 * s + 1) * cs], rel1s[s]);
    }
    // cell_map: channels 264, 265
    __stcs(&out[opix + (size_t)264 * cs], cell[b * 2 + 0] * (float)HH);
    __stcs(&out[opix + (size_t)265 * cs], cell[b * 2 + 1] * (float)WW);

    // ---- cooperative tile load: nr x nc pixels, 64 ch each, float4 coalesced ----
    {
        const float* __restrict__ xTb = g_xT + (size_t)b * HH * WW * CC;
        const int ntot = nr * nc * 16;
        for (int i = tid; i < ntot; i += 256) {
            int p  = i >> 4;
            int cg = (i & 15) << 2;
            int py = p / nc, px = p - py * nc;
            const float4 v = *reinterpret_cast<const float4*>(
                xTb + (size_t)((rowLo + py) * WW + (colLo + px)) * CC + cg);
            *reinterpret_cast<float4*>(&tile[p * TP + cg]) = v;
        }
    }
    __syncthreads();

    // tile offsets for this thread's 3x3 patch (defensively clamped)
    int toff[9];
#pragma unroll
    for (int jy = 0; jy < 3; jy++) {
        int ty = min(max(ryc[jy] - rowLo, 0), nr - 1);
#pragma unroll
        for (int jx = 0; jx < 3; jx++) {
            int tx = min(max(rxc[jx] - colLo, 0), nc - 1);
            toff[jy * 3 + jx] = (ty * nc + tx) * TP;
        }
    }

    const float ay00 = ay[0][0], ay01 = ay[0][1];                 // ay[0][2] == 0
    const float ay10 = ay[1][0], ay11 = ay[1][1], ay12 = ay[1][2];

    // feats: channels 8 + s*64 + c ; 9 SMEM loads serve all 4 shifts
#pragma unroll 2
    for (int c = 0; c < CC; c += 4) {
        float4 t0[3], t1[3];
#pragma unroll
        for (int jx = 0; jx < 3; jx++) {
            const float4 f0 = *reinterpret_cast<const float4*>(&tile[toff[0 + jx] + c]);
            const float4 f1 = *reinterpret_cast<const float4*>(&tile[toff[3 + jx] + c]);
            const float4 f2 = *reinterpret_cast<const float4*>(&tile[toff[6 + jx] + c]);
            t0[jx].x = ay00 * f0.x + ay01 * f1.x;
            t0[jx].y = ay00 * f0.y + ay01 * f1.y;
            t0[jx].z = ay00 * f0.z + ay01 * f1.z;
            t0[jx].w = ay00 * f0.w + ay01 * f1.w;
            t1[jx].x = ay10 * f0.x + ay11 * f1.x + ay12 * f2.x;
            t1[jx].y = ay10 * f0.y + ay11 * f1.y + ay12 * f2.y;
            t1[jx].z = ay10 * f0.z + ay11 * f1.z + ay12 * f2.z;
            t1[jx].w = ay10 * f0.w + ay11 * f1.w + ay12 * f2.w;
        }
#pragma unroll
        for (int s = 0; s < 4; s++) {
            const float4* ts = (s < 2) ? t0 : t1;
            const float w0 = axw[s][0], w1 = axw[s][1], w2 = axw[s][2];
            float4 acc;
            acc.x = w0 * ts[0].x + w1 * ts[1].x + w2 * ts[2].x;
            acc.y = w0 * ts[0].y + w1 * ts[1].y + w2 * ts[2].y;
            acc.z = w0 * ts[0].z + w1 * ts[1].z + w2 * ts[2].z;
            acc.w = w0 * ts[0].w + w1 * ts[1].w + w2 * ts[2].w;
            const size_t och = opix + (size_t)(8 + s * 64 + c) * cs;
            __stcs(&out[och + 0 * cs], acc.x);
            __stcs(&out[och + 1 * cs], acc.y);
            __stcs(&out[och + 2 * cs], acc.z);
            __stcs(&out[och + 3 * cs], acc.w);
        }
    }
}

extern "C" void kernel_launch(void* const* d_in, const int* in_sizes, int n_in,
                              void* d_out, int out_size) {
    const float* x     = (const float*)d_in[0];   // (4,64,80,80)
    const float* coord = (const float*)d_in[1];   // (4,320,320,2)
    const float* cell  = (const float*)d_in[2];   // (4,2)
    float* out = (float*)d_out;                   // (4,266,320,320)

    {
        int n = BB * HH * WW;
        transpose_kernel<<<(n + 255) / 256, 256>>>(x);
    }
    {
        dim3 block(32, 8);
        dim3 grid(WO / 32, HO / 8, BB);
        liif_kernel<<<grid, block>>>(coord, cell, out);
    }
}